// round 16
// baseline (speedup 1.0000x reference)
#include <cuda_runtime.h>
#include <cstdint>
#include <cstddef>

#define BB 64
#define TT 512
#define DD 600
#define DA 300
#define UU 300
#define HH 5
#define EPS_F 1e-7f
#define NCH 8          // t-chunks in fused pass
#define TCH (TT/NCH)   // 64 t per chunk
#define GRB 75         // recurrence grid (all co-resident, <=148 SMs)

// fused v5 dynamic smem (floats): rows ring 3*600 float4 = 7200 fl, lpart 80, wexp 40
#define FUSED_SMEM_FLOATS (7200 + 80 + 40)
#define FUSED_SMEM_BYTES  (FUSED_SMEM_FLOATS * 4)
// dynamic smem for recur_kernel: e_sh[19200] + w1[8*308] + w2[4*308]
#define RECUR_SMEM_FLOATS (19200 + 8 * 308 + 4 * 308)
#define RECUR_SMEM_BYTES  (RECUR_SMEM_FLOATS * 4)

// ---------------- device scratch ----------------
__device__ float g_IALpart[NCH * HH * BB * DD];   // per-chunk partial unnormalized i_al
__device__ float g_Zpart[NCH * HH * BB];          // per-chunk partial sum of exp
__device__ float g_IAL[HH * BB * DD];             // normalized i_al
__device__ float g_Pconst[HH * BB * 900];         // [r|z|c] preacts from i_al
__device__ float4 g_e4[BB * UU / 4];              // recurrent state (16B aligned)
__device__ float4 g_rE4[BB * UU / 4];             // r * e
__device__ float g_z[BB * UU];                    // z gate
__device__ unsigned g_cnt = 0;                    // grid barrier counter
__device__ volatile unsigned g_gen = 0;           // grid barrier generation

__device__ __forceinline__ void cp_async16(void* smem_dst, const void* gmem_src) {
    unsigned sdst = (unsigned)__cvta_generic_to_shared(smem_dst);
    asm volatile("cp.async.cg.shared.global [%0], [%1], 16;" :: "r"(sdst), "l"(gmem_src));
}
#define CP_COMMIT() asm volatile("cp.async.commit_group;")

// ---------------- kernel 1: fused v5 — ws in registers, per-thread complete macc ----------
// grid (NCH, BB) x 256. Block: 64 rows of batch b, 16 groups of 4 rows, 3-deep cp.async ring.
// Warp w: row w>>1, d-half (w&1)*300. Lane preloads its ws slice (<=15 float4) ONCE.
// Stage A: half-logit partials -> lpart; exp on even-warp lane0 -> wexp.
// Stage B: every thread accumulates its d-slices (tid, tid+256, tid+512) over all 4 rows.
__global__ void __launch_bounds__(256, 2)
fused_kernel(const float* __restrict__ memory, const float* __restrict__ al_w) {
    extern __shared__ float sm[];
    float4* rows4 = (float4*)sm;        // 3 buffers x 600 float4 (4 rows x 150)
    float* lpart = sm + 7200;           // [row][half][h] = row*10 + half*5 + h
    float* wexp  = sm + 7280;           // [row][h] = row*5 + h

    int chunk = blockIdx.x;
    int b = blockIdx.y;
    int tid = threadIdx.x;
    int wid = tid >> 5;
    int lane = tid & 31;
    int row = wid >> 1;       // 0..3 within group
    int half = wid & 1;

    // preload ws slice into registers (<=15 float4): i4 = half*75 + lane + 32j
    const float4* alw4 = (const float4*)al_w;   // 300 float4 per h-row
    float4 wreg[HH][3];
    bool jv[3];
#pragma unroll
    for (int j = 0; j < 3; j++) {
        int s = lane + 32 * j;
        jv[j] = (s < 75);
#pragma unroll
        for (int h = 0; h < HH; h++) {
            if (jv[j]) wreg[h][j] = __ldg(alw4 + h * 300 + half * 75 + s);
            else       wreg[h][j] = make_float4(0.f, 0.f, 0.f, 0.f);
        }
    }

    const float4* gbase = (const float4*)(memory + ((size_t)b * TT + chunk * TCH) * DD);

    // prologue: prefetch groups 0 and 1 (600 float4 each)
#pragma unroll
    for (int g = 0; g < 2; g++) {
#pragma unroll
        for (int i = 0; i < 3; i++) {
            int idx = tid + 256 * i;
            if (idx < 600) cp_async16(&rows4[g * 600 + idx], gbase + g * 600 + idx);
        }
        CP_COMMIT();
    }

    int d0 = tid, d1 = tid + 256, d2 = tid + 512;
    bool has2 = (d2 < DD);
    float macc[HH][3];
#pragma unroll
    for (int h = 0; h < HH; h++) { macc[h][0]=0.f; macc[h][1]=0.f; macc[h][2]=0.f; }
    float zacc = 0.f;   // valid on tid<5 (h = tid)

#pragma unroll 1
    for (int g = 0; g < 16; g++) {
        int buf = g % 3;
        if (g < 14) {
            int nbuf = (g + 2) % 3;
#pragma unroll
            for (int i = 0; i < 3; i++) {
                int idx = tid + 256 * i;
                if (idx < 600) cp_async16(&rows4[nbuf * 600 + idx], gbase + (g + 2) * 600 + idx);
            }
            CP_COMMIT();
            asm volatile("cp.async.wait_group 2;");
        } else {
            asm volatile("cp.async.wait_group %0;" :: "n"(0) : "memory");
        }
        __syncthreads();

        // ---- stage A: half-logit partials (warp = row x half) ----
        {
            const float4* rr = rows4 + buf * 600 + row * 150 + half * 75;
            float acc[HH] = {0.f, 0.f, 0.f, 0.f, 0.f};
#pragma unroll
            for (int j = 0; j < 3; j++) {
                if (jv[j]) {
                    float4 m = rr[lane + 32 * j];
#pragma unroll
                    for (int h = 0; h < HH; h++) {
                        float4 w = wreg[h][j];
                        acc[h] += m.x*w.x + m.y*w.y + m.z*w.z + m.w*w.w;
                    }
                }
            }
#pragma unroll
            for (int h = 0; h < HH; h++) {
#pragma unroll
                for (int off = 16; off > 0; off >>= 1)
                    acc[h] += __shfl_xor_sync(0xffffffffu, acc[h], off);
            }
            if (lane == 0) {
#pragma unroll
                for (int h = 0; h < HH; h++) lpart[row * 10 + half * 5 + h] = acc[h];
            }
        }
        __syncthreads();
        // exp on even warps' lane0
        if (half == 0 && lane == 0) {
#pragma unroll
            for (int h = 0; h < HH; h++)
                wexp[row * 5 + h] = expf(lpart[row * 10 + h] + lpart[row * 10 + 5 + h]);
        }
        __syncthreads();
        // ---- zacc (threads 0..4, h = tid) ----
        if (tid < HH)
            zacc += wexp[tid] + wexp[5 + tid] + wexp[10 + tid] + wexp[15 + tid];
        // ---- stage B: accumulate my d-slices over 4 rows ----
        {
            const float* rf = (const float*)(rows4 + buf * 600);
#pragma unroll
            for (int r = 0; r < 4; r++) {
                float m0 = rf[r * DD + d0];
                float m1 = rf[r * DD + d1];
                float m2 = has2 ? rf[r * DD + d2] : 0.f;
#pragma unroll
                for (int h = 0; h < HH; h++) {
                    float a = wexp[r * 5 + h];
                    macc[h][0] += a * m0;
                    macc[h][1] += a * m1;
                    macc[h][2] += a * m2;
                }
            }
        }
        __syncthreads();
    }

    // ---- write per-thread-complete partials ----
#pragma unroll
    for (int h = 0; h < HH; h++) {
        float* dst = g_IALpart + ((size_t)(chunk * HH + h) * BB + b) * DD;
        dst[d0] = macc[h][0];
        dst[d1] = macc[h][1];
        if (has2) dst[d2] = macc[h][2];
    }
    if (tid < HH)
        g_Zpart[(chunk * HH + tid) * BB + b] = zacc;
}

// ---------------- kernel 2: reduce partials + normalize (deterministic) ----------------
__global__ void reduce_ial_kernel() {
    int i = blockIdx.x * 256 + threadIdx.x;
    int hb = i / DD;
    int h = hb / BB;
    int b = hb - h * BB;
    float s = 0.f;
#pragma unroll
    for (int c = 0; c < NCH; c++) s += g_IALpart[(size_t)c * (HH * BB * DD) + i];
    float z = 0.f;
#pragma unroll
    for (int c = 0; c < NCH; c++) z += g_Zpart[(c * HH + h) * BB + b];
    g_IAL[i] = s / (z + EPS_F);
}

// ---------------- kernel 3: Pconst = IAL @ [Wr|Wz|Wx]  (M=320, K=600, N=900) ----------------
__global__ void pconst_kernel(const float* __restrict__ wr, const float* __restrict__ wz,
                              const float* __restrict__ wx) {
    __shared__ float Xs[32][65];
    __shared__ float Ws[32][33];
    int n0 = blockIdx.x * 32;
    int h = blockIdx.y;
    int tid = threadIdx.x;
    int tu = tid & 15;
    int tb = tid >> 4;

    float acc[4][2] = {};
    for (int kc = 0; kc < DD; kc += 32) {
        {
            int kk = tid & 31;
            int br = tid >> 5;
            int k = kc + kk;
#pragma unroll
            for (int j = 0; j < 8; j++) {
                int b = br + 8 * j;
                Xs[kk][b] = (k < DD) ? g_IAL[((size_t)(h * BB + b)) * DD + k] : 0.f;
            }
        }
        {
            int u = tid & 31;
            int kr = tid >> 5;
            int n = n0 + u;
#pragma unroll
            for (int j = 0; j < 4; j++) {
                int kk2 = kr + 8 * j;
                int kg = kc + kk2;
                float v = 0.f;
                if (kg < DD && n < 900) {
                    if (n < 300)      v = wr[kg * UU + n];
                    else if (n < 600) v = wz[kg * UU + (n - 300)];
                    else              v = wx[kg * UU + (n - 600)];
                }
                Ws[kk2][u] = v;
            }
        }
        __syncthreads();
#pragma unroll
        for (int kk3 = 0; kk3 < 32; kk3++) {
            float xv[4], wv[2];
#pragma unroll
            for (int i = 0; i < 4; i++) xv[i] = Xs[kk3][tb * 4 + i];
#pragma unroll
            for (int j = 0; j < 2; j++) wv[j] = Ws[kk3][tu * 2 + j];
#pragma unroll
            for (int i = 0; i < 4; i++)
#pragma unroll
                for (int j = 0; j < 2; j++) acc[i][j] += xv[i] * wv[j];
        }
        __syncthreads();
    }
#pragma unroll
    for (int i = 0; i < 4; i++) {
        int b = tb * 4 + i;
#pragma unroll
        for (int j = 0; j < 2; j++) {
            int n = n0 + tu * 2 + j;
            if (n < 900) g_Pconst[((size_t)(h * BB + b)) * 900 + n] = acc[i][j];
        }
    }
}

// ---------------- grid barrier (proven: atomicAdd + volatile generation) ----------
__device__ __forceinline__ void grid_barrier() {
    __syncthreads();
    if (threadIdx.x == 0) {
        __threadfence();
        unsigned my = g_gen;
        if (atomicAdd(&g_cnt, 1) == GRB - 1) {
            g_cnt = 0;
            __threadfence();
            g_gen = my + 1;
        } else {
            while (g_gen == my) { }
        }
    }
    __syncthreads();
}

// ---------------- kernel 4: persistent GRU recurrence (R15, proven) ----------------
__global__ void __launch_bounds__(512, 1)
recur_kernel(const float* __restrict__ ur, const float* __restrict__ uz,
             const float* __restrict__ wg, float* __restrict__ out) {
    extern __shared__ float rs[];
    float* e_sh = rs;                    // 19200 floats
    float4* e4 = (float4*)rs;            // 4800 float4
    float* w1_sh = rs + 19200;           // 8 * 308
    float* w2_sh = rs + 19200 + 8 * 308; // 4 * 308

    int tid = threadIdx.x;
    int bid = blockIdx.x;

    for (int i = tid; i < 2400; i += 512) {
        int k = i >> 3, j = i & 7;
        int n = bid * 8 + j;
        float v = (n < 300) ? ur[k * UU + n] : uz[k * UU + (n - 300)];
        w1_sh[j * 308 + k] = v;
    }
    for (int i = tid; i < 1200; i += 512) {
        int k = i >> 2, j = i & 3;
        w2_sh[j * 308 + k] = wg[k * UU + bid * 4 + j];
    }

    int n1 = bid * 8 + (tid & 7);
    int b1 = tid >> 3;
    int n2 = bid * 4 + (tid & 3);
    int b2 = tid >> 2;
    const float4* wv1 = (const float4*)(w1_sh + (tid & 7) * 308);
    const float4* wv2 = (const float4*)(w2_sh + (tid & 3) * 308);

    // ---- hop 1: elementwise (e0 = 0 => e1 = sigmoid(Pz) * tanh(Pc)) ----
    if (tid < 256) {
        float pz = __ldg(g_Pconst + (size_t)b2 * 900 + 300 + n2);
        float pc = __ldg(g_Pconst + (size_t)b2 * 900 + 600 + n2);
        float z = 1.0f / (1.0f + expf(-pz));
        float e1 = z * tanhf(pc);
        asm volatile("st.global.cg.f32 [%0], %1;"
                     :: "l"((float*)g_e4 + b2 * UU + n2), "f"(e1));
    }
    grid_barrier();

    // ---- hops 2..5 ----
#pragma unroll 1
    for (int h = 1; h < HH; h++) {
        // phase 1: r,z = sigmoid(Pconst + e @ [Ur|Uz])
        {
            float p;
            asm volatile("ld.global.nc.f32 %0, [%1];" : "=f"(p)
                         : "l"(g_Pconst + ((size_t)(h * BB + b1)) * 900 + n1));
            for (int i = tid; i < 4800; i += 512)
                e4[i] = __ldcg(g_e4 + i);
            __syncthreads();
            const float4* ev = e4 + b1 * 75;
            float ax = 0.f, ay = 0.f, az = 0.f, aw = 0.f;
#pragma unroll
            for (int qq = 0; qq < 75; qq++) {
                float4 e = ev[qq];
                float4 w = wv1[qq];
                ax += e.x * w.x; ay += e.y * w.y;
                az += e.z * w.z; aw += e.w * w.w;
            }
            float acc = (ax + ay) + (az + aw);
            float s = 1.0f / (1.0f + expf(-(p + acc)));
            if (n1 < 300) {
                float ev1 = e_sh[b1 * UU + n1];
                __stcg((float*)g_rE4 + b1 * UU + n1, s * ev1);
            } else {
                __stcg(g_z + b1 * UU + (n1 - 300), s);
            }
        }
        grid_barrier();
        // phase 2: e = (1-z)e + z*tanh(Pconst_c + rE @ Wg)
        {
            float p = 0.f;
            if (tid < 256)
                asm volatile("ld.global.nc.f32 %0, [%1];" : "=f"(p)
                             : "l"(g_Pconst + ((size_t)(h * BB + b2)) * 900 + 600 + n2));
            for (int i = tid; i < 4800; i += 512)
                e4[i] = __ldcg(g_rE4 + i);
            __syncthreads();
            if (tid < 256) {
                const float4* rv = e4 + b2 * 75;
                float ax = 0.f, ay = 0.f, az = 0.f, aw = 0.f;
#pragma unroll
                for (int qq = 0; qq < 75; qq++) {
                    float4 r = rv[qq];
                    float4 w = wv2[qq];
                    ax += r.x * w.x; ay += r.y * w.y;
                    az += r.z * w.z; aw += r.w * w.w;
                }
                float acc = (ax + ay) + (az + aw);
                float et = tanhf(p + acc);
                float zv, ev;
                float* ep = (float*)g_e4 + b2 * UU + n2;
                asm volatile("ld.global.cg.f32 %0, [%1];" : "=f"(ev) : "l"(ep));
                asm volatile("ld.global.cg.f32 %0, [%1];" : "=f"(zv) : "l"(g_z + b2 * UU + n2));
                float o = (1.0f - zv) * ev + zv * et;
                if (h == HH - 1) {
                    out[b2 * UU + n2] = o;
                } else {
                    asm volatile("st.global.cg.f32 [%0], %1;" :: "l"(ep), "f"(o));
                }
            }
            if (h < HH - 1) grid_barrier();
        }
    }
}

// ---------------- launch ----------------
extern "C" void kernel_launch(void* const* d_in, const int* in_sizes, int n_in,
                              void* d_out, int out_size) {
    const float* memory = nullptr;  // 19660800
    const float* al_w   = nullptr;  // 6000
    const float* w180[3] = {nullptr, nullptr, nullptr};  // wr, wz, wx
    const float* w90[3]  = {nullptr, nullptr, nullptr};  // ur, uz, wg
    int n180 = 0, n90 = 0;
    for (int i = 0; i < n_in; i++) {
        const float* p = (const float*)d_in[i];
        switch (in_sizes[i]) {
            case 19660800: memory = p; break;
            case 6000:     al_w = p;   break;
            case 180000:   if (n180 < 3) w180[n180++] = p; break;
            case 90000:    if (n90 < 3)  w90[n90++]  = p; break;
            default: break;
        }
    }
    const float* gru_wr = w180[0];
    const float* gru_wz = w180[1];
    const float* gru_wx = w180[2];
    const float* gru_ur = w90[0];
    const float* gru_uz = w90[1];
    const float* gru_wg = w90[2];
    float* out = (float*)d_out;

    cudaFuncSetAttribute(fused_kernel, cudaFuncAttributeMaxDynamicSharedMemorySize,
                         FUSED_SMEM_BYTES);
    cudaFuncSetAttribute(recur_kernel, cudaFuncAttributeMaxDynamicSharedMemorySize,
                         RECUR_SMEM_BYTES);

    fused_kernel<<<dim3(NCH, BB), 256, FUSED_SMEM_BYTES>>>(memory, al_w);
    reduce_ial_kernel<<<(HH * BB * DD) / 256, 256>>>();
    pconst_kernel<<<dim3(29, HH), 256>>>(gru_wr, gru_wz, gru_wx);
    recur_kernel<<<GRB, 512, RECUR_SMEM_BYTES>>>(gru_ur, gru_uz, gru_wg, out);
}